// round 1
// baseline (speedup 1.0000x reference)
#include <cuda_runtime.h>
#include <math.h>

// ---------------------------------------------------------------------------
// LSTM_80831284510999 — round 0: fp32 register-tiled SGEMM baseline
//
// Stage 1: gates[B,4H] = act( concat(emb,hid,ctx)[B,3072] @ [Wi;Wf;Wo;Wg]^T + b )
//          (sigmoid for i,f,o; tanh for g) — fused epilogue
// Stage 2: cell = f*prev_cell + i*g ; hidden = o*tanh(cell)   (pointwise)
// Stage 3: resid = emb + hidden@Wh^T + bh + ctx@Wc^T + bc     (K-seg GEMM)
// Stage 4: pred  = resid@Wp^T + bp                            (GEMM)
// ---------------------------------------------------------------------------

#define BM 128
#define BN 128
#define BK 16

// Scratch (allocation-free rule: __device__ globals)
__device__ float g_gates[4096u * 4096u];   // [B, 4H] activated gates
__device__ float g_resid[4096u * 1024u];   // [B, E]

struct GemmArgs {
    const float* A0; const float* A1; const float* A2;     // A segments (1024 cols each)
    const float* W0; const float* W1; const float* W2; const float* W3;
    const float* b0; const float* b1; const float* b2; const float* b3;
    const float* add;                                      // optional [M,N] addend
    float* out;
    int K; int N;
};

__device__ __forceinline__ float sigmoidf_(float x) { return 1.0f / (1.0f + expf(-x)); }

// WMODE 0: W segmented along N (gate index = n>>10), W row stride = K (3072)
// WMODE 1: W segmented along K (seg = k>>10),        W row stride = 1024
// EPI 0: gate activation epilogue (bias per gate; sigmoid/sigmoid/sigmoid/tanh)
// EPI 1: out = acc + b0[n] (+ b1[n]) (+ add[m*N+n])
template <int WMODE, int EPI>
__global__ void __launch_bounds__(256) gemm_kernel(GemmArgs a)
{
    __shared__ float As[BK][BM];
    __shared__ float Ws[BK][BN];

    const int tid = threadIdx.x;
    const int m0 = blockIdx.y * BM;
    const int n0 = blockIdx.x * BN;
    const int tx = tid & 15;     // n direction
    const int ty = tid >> 4;     // m direction

    float acc[8][8];
#pragma unroll
    for (int i = 0; i < 8; i++)
#pragma unroll
        for (int j = 0; j < 8; j++) acc[i][j] = 0.0f;

    // For WMODE 0 the W segment is fixed per block (BN=128 divides 1024)
    const float* WbaseN = nullptr;
    int nrow0 = 0;
    if (WMODE == 0) {
        const int nseg = n0 >> 10;
        WbaseN = (nseg == 0) ? a.W0 : (nseg == 1) ? a.W1 : (nseg == 2) ? a.W2 : a.W3;
        nrow0 = n0 & 1023;
    }

    for (int k0 = 0; k0 < a.K; k0 += BK) {
        const int kseg = k0 >> 10;
        const int koff = k0 & 1023;
        const float* Abase = (kseg == 0) ? a.A0 : (kseg == 1) ? a.A1 : a.A2;
        const float* Wkbase = nullptr;
        if (WMODE == 1)
            Wkbase = (kseg == 0) ? a.W0 : (kseg == 1) ? a.W1 : a.W2;

#pragma unroll
        for (int it = 0; it < 2; it++) {
            const int f = tid + it * 256;
            const int row = f >> 2;            // 0..127
            const int kc = (f & 3) * 4;        // 0,4,8,12

            float4 av = *reinterpret_cast<const float4*>(
                Abase + (m0 + row) * 1024 + koff + kc);
            As[kc + 0][row] = av.x; As[kc + 1][row] = av.y;
            As[kc + 2][row] = av.z; As[kc + 3][row] = av.w;

            float4 wv;
            if (WMODE == 0)
                wv = *reinterpret_cast<const float4*>(
                    WbaseN + (nrow0 + row) * a.K + k0 + kc);
            else
                wv = *reinterpret_cast<const float4*>(
                    Wkbase + (n0 + row) * 1024 + koff + kc);
            Ws[kc + 0][row] = wv.x; Ws[kc + 1][row] = wv.y;
            Ws[kc + 2][row] = wv.z; Ws[kc + 3][row] = wv.w;
        }
        __syncthreads();

#pragma unroll
        for (int kk = 0; kk < BK; kk++) {
            float af[8], wf[8];
#pragma unroll
            for (int i = 0; i < 8; i += 4) {
                float4 v = *reinterpret_cast<const float4*>(&As[kk][ty * 8 + i]);
                af[i] = v.x; af[i + 1] = v.y; af[i + 2] = v.z; af[i + 3] = v.w;
            }
#pragma unroll
            for (int j = 0; j < 8; j += 4) {
                float4 v = *reinterpret_cast<const float4*>(&Ws[kk][tx * 8 + j]);
                wf[j] = v.x; wf[j + 1] = v.y; wf[j + 2] = v.z; wf[j + 3] = v.w;
            }
#pragma unroll
            for (int i = 0; i < 8; i++)
#pragma unroll
                for (int j = 0; j < 8; j++)
                    acc[i][j] += af[i] * wf[j];
        }
        __syncthreads();
    }

    const int N = a.N;
    if (EPI == 0) {
        const int gate = n0 >> 10;
        const float* bias = (gate == 0) ? a.b0 : (gate == 1) ? a.b1
                          : (gate == 2) ? a.b2 : a.b3;
#pragma unroll
        for (int i = 0; i < 8; i++) {
            const int m = m0 + ty * 8 + i;
#pragma unroll
            for (int j = 0; j < 8; j++) {
                const int n = n0 + tx * 8 + j;
                float v = acc[i][j] + bias[n & 1023];
                v = (gate < 3) ? sigmoidf_(v) : tanhf(v);
                a.out[m * N + n] = v;
            }
        }
    } else {
#pragma unroll
        for (int i = 0; i < 8; i++) {
            const int m = m0 + ty * 8 + i;
#pragma unroll
            for (int j = 0; j < 8; j++) {
                const int n = n0 + tx * 8 + j;
                float v = acc[i][j] + a.b0[n];
                if (a.b1)  v += a.b1[n];
                if (a.add) v += a.add[m * N + n];
                a.out[m * N + n] = v;
            }
        }
    }
}

__global__ void lstm_pointwise(const float* __restrict__ gates,
                               const float* __restrict__ prev_cell,
                               float* __restrict__ hidden,
                               float* __restrict__ cell)
{
    const int idx = blockIdx.x * blockDim.x + threadIdx.x;
    if (idx >= 4096 * 1024) return;
    const int m = idx >> 10;
    const int h = idx & 1023;
    const float* gr = gates + (size_t)m * 4096;
    const float i = gr[h];
    const float f = gr[1024 + h];
    const float o = gr[2048 + h];
    const float g = gr[3072 + h];
    const float c = f * prev_cell[idx] + i * g;
    cell[idx] = c;
    hidden[idx] = o * tanhf(c);
}

extern "C" void kernel_launch(void* const* d_in, const int* in_sizes, int n_in,
                              void* d_out, int out_size)
{
    const float* emb = (const float*)d_in[0];   // previous_embedded_caption [B,E]
    const float* hid = (const float*)d_in[1];   // previous_hidden_state    [B,H]
    const float* pc  = (const float*)d_in[2];   // previous_cell_state      [B,H]
    const float* ctx = (const float*)d_in[3];   // current_context_vector   [B,C]
    const float* Wi = (const float*)d_in[4];  const float* bi = (const float*)d_in[5];
    const float* Wf = (const float*)d_in[6];  const float* bf = (const float*)d_in[7];
    const float* Wo = (const float*)d_in[8];  const float* bo = (const float*)d_in[9];
    const float* Wg = (const float*)d_in[10]; const float* bg = (const float*)d_in[11];
    const float* Wc = (const float*)d_in[12]; const float* bc = (const float*)d_in[13];
    const float* Wh = (const float*)d_in[14]; const float* bh = (const float*)d_in[15];
    const float* Wp = (const float*)d_in[16]; const float* bp = (const float*)d_in[17];

    const int B = 4096, E = 1024, H = 1024;
    float* out    = (float*)d_out;
    float* pred   = out;                    // [B,E]
    float* hidden = out + (size_t)B * E;    // [B,H]
    float* cell   = out + (size_t)B * E + (size_t)B * H;  // [B,H]

    float* gates = nullptr;
    float* resid = nullptr;
    cudaGetSymbolAddress((void**)&gates, g_gates);
    cudaGetSymbolAddress((void**)&resid, g_resid);

    // Stage 1: gates GEMM (M=4096, N=4096, K=3072), fused activation
    {
        GemmArgs a = {};
        a.A0 = emb; a.A1 = hid; a.A2 = ctx;
        a.W0 = Wi;  a.W1 = Wf;  a.W2 = Wo;  a.W3 = Wg;
        a.b0 = bi;  a.b1 = bf;  a.b2 = bo;  a.b3 = bg;
        a.out = gates; a.K = 3072; a.N = 4096;
        gemm_kernel<0, 0><<<dim3(32, 32), 256>>>(a);
    }

    // Stage 2: pointwise LSTM update -> hidden, cell (directly into d_out)
    lstm_pointwise<<<(B * H + 255) / 256, 256>>>(gates, pc, hidden, cell);

    // Stage 3: resid = emb + hidden@Wh^T + bh + ctx@Wc^T + bc  (M=4096,N=1024,K=2048)
    {
        GemmArgs a = {};
        a.A0 = hidden; a.A1 = ctx;
        a.W0 = Wh;     a.W1 = Wc;
        a.b0 = bh;     a.b1 = bc;
        a.add = emb;
        a.out = resid; a.K = 2048; a.N = 1024;
        gemm_kernel<1, 1><<<dim3(8, 32), 256>>>(a);
    }

    // Stage 4: pred = resid@Wp^T + bp  (M=4096,N=1024,K=1024)
    {
        GemmArgs a = {};
        a.A0 = resid;
        a.W0 = Wp;
        a.b0 = bp;
        a.out = pred; a.K = 1024; a.N = 1024;
        gemm_kernel<1, 1><<<dim3(8, 32), 256>>>(a);
    }
}

// round 3
// speedup vs baseline: 2.0159x; 2.0159x over previous
#include <cuda_runtime.h>
#include <cstdint>
#include <math.h>

// ---------------------------------------------------------------------------
// LSTM_80831284510999 — round 2: mma.sync tf32 (sm_80-class HMMA; base ISA,
// no 'a'-suffix features — ptxas target is sm_103 plain).
// CTA tile 128x128, BK=32, 8 warps (2x4) x warp tile 64x32, double-buffered
// SMEM, cvt.rna.tf32 pre-rounding (kills HW-truncation bias).
// ---------------------------------------------------------------------------

static constexpr int ROWPAD = 36;                   // 36 words/row: frag reads + STS.128 conflict-free
static constexpr int BUF_FLOATS = 128 * ROWPAD;     // 4608 floats per tile buffer
static constexpr int SMEM_BYTES = 4 * BUF_FLOATS * 4;  // A0,A1,B0,B1 = 73728 B

// Scratch (allocation-free rule)
__device__ float g_gates[4096ull * 4096ull];
__device__ float g_resid[4096ull * 1024ull];

__device__ __forceinline__ float f2tf32(float x) {
    uint32_t u; asm("cvt.rna.tf32.f32 %0, %1;" : "=r"(u) : "f"(x));
    return __uint_as_float(u);
}

struct TArgs {
    const float* aseg[3];   // A K-segments, each [4096, 1024] row-major
    const float* w[4];      // W segments
    const float* bias[4];
    const float* add;       // optional [M,1024] addend (EPI 1)
    float* out;
    int K;
    int Nout;
    int wn_mode;            // 1: W seg by gate (row stride 3072), 0: by kseg (stride 1024)
};

// EPI 0: gates (bias + sigmoid/sigmoid/sigmoid/tanh by n>>10)
// EPI 1: + bias0[n] + bias1[n] + add[m,n]
// EPI 2: + bias0[n]
template <int EPI>
__global__ void __launch_bounds__(256, 1) gemm_mma(TArgs a)
{
    extern __shared__ float sm[];
    float* Abuf[2] = { sm,                sm + BUF_FLOATS };
    float* Bbuf[2] = { sm + 2 * BUF_FLOATS, sm + 3 * BUF_FLOATS };

    const int tid  = threadIdx.x;
    const int m0   = blockIdx.x * 128;
    const int n0   = blockIdx.y * 128;
    const int wid  = tid >> 5, lane = tid & 31;
    const int mw   = (wid >> 2) * 64;     // warp m offset in tile
    const int nw   = (wid & 3) * 32;      // warp n offset in tile
    const int q    = lane >> 2, r = lane & 3;

    const int NC = a.K >> 5;

    float acc[4][4][4];
#pragma unroll
    for (int i = 0; i < 4; i++)
#pragma unroll
        for (int j = 0; j < 4; j++)
#pragma unroll
            for (int e = 0; e < 4; e++) acc[i][j][e] = 0.0f;

    float4 av[4], wv[4];

    // ---- stage chunk: LDG into regs ----
    auto ldg_chunk = [&](int c) {
        const int k0 = c * 32;
        const float* ab = a.aseg[k0 >> 10] + (size_t)m0 * 1024 + (k0 & 1023);
        const float* wb; int ws;
        if (a.wn_mode) { wb = a.w[n0 >> 10] + (size_t)(n0 & 1023) * 3072 + k0; ws = 3072; }
        else           { wb = a.w[k0 >> 10] + (size_t)n0 * 1024 + (k0 & 1023); ws = 1024; }
#pragma unroll
        for (int t = 0; t < 4; t++) {
            const int id = tid + t * 256;
            const int m = id >> 3, kq = id & 7;
            av[t] = *(const float4*)(ab + (size_t)m * 1024 + kq * 4);
            wv[t] = *(const float4*)(wb + (size_t)m * ws   + kq * 4);
        }
    };
    // ---- cvt + STS into buffer b ----
    auto sts_chunk = [&](int b) {
        float* A = Abuf[b]; float* B = Bbuf[b];
#pragma unroll
        for (int t = 0; t < 4; t++) {
            const int id = tid + t * 256;
            const int m = id >> 3, kq = id & 7;
            *(float4*)(A + m * ROWPAD + kq * 4) = make_float4(
                f2tf32(av[t].x), f2tf32(av[t].y), f2tf32(av[t].z), f2tf32(av[t].w));
            *(float4*)(B + m * ROWPAD + kq * 4) = make_float4(
                f2tf32(wv[t].x), f2tf32(wv[t].y), f2tf32(wv[t].z), f2tf32(wv[t].w));
        }
    };
    // ---- MMA over buffer b (4 k8 steps) ----
    auto mma_chunk = [&](int b) {
        const float* A = Abuf[b]; const float* B = Bbuf[b];
#pragma unroll
        for (int kk = 0; kk < 32; kk += 8) {
            uint32_t af[4][4], bf[4][2];
#pragma unroll
            for (int mt = 0; mt < 4; mt++) {
                const int base = (mw + mt * 16 + q) * ROWPAD + kk + r;
                af[mt][0] = __float_as_uint(A[base]);
                af[mt][1] = __float_as_uint(A[base + 8 * ROWPAD]);
                af[mt][2] = __float_as_uint(A[base + 4]);
                af[mt][3] = __float_as_uint(A[base + 8 * ROWPAD + 4]);
            }
#pragma unroll
            for (int nt = 0; nt < 4; nt++) {
                const int base = (nw + nt * 8 + q) * ROWPAD + kk + r;
                bf[nt][0] = __float_as_uint(B[base]);
                bf[nt][1] = __float_as_uint(B[base + 4]);
            }
#pragma unroll
            for (int mt = 0; mt < 4; mt++)
#pragma unroll
                for (int nt = 0; nt < 4; nt++) {
                    asm volatile(
                        "mma.sync.aligned.m16n8k8.row.col.f32.tf32.tf32.f32 "
                        "{%0,%1,%2,%3}, {%4,%5,%6,%7}, {%8,%9}, {%0,%1,%2,%3};"
                        : "+f"(acc[mt][nt][0]), "+f"(acc[mt][nt][1]),
                          "+f"(acc[mt][nt][2]), "+f"(acc[mt][nt][3])
                        : "r"(af[mt][0]), "r"(af[mt][1]), "r"(af[mt][2]), "r"(af[mt][3]),
                          "r"(bf[nt][0]), "r"(bf[nt][1]));
                }
        }
    };

    ldg_chunk(0);
    sts_chunk(0);
    __syncthreads();
    for (int c = 0; c < NC; c++) {
        if (c + 1 < NC) ldg_chunk(c + 1);
        mma_chunk(c & 1);
        if (c + 1 < NC) sts_chunk((c + 1) & 1);
        __syncthreads();
    }

    // ---- epilogue: register accumulators -> fused bias/act -> global ----
    const int gate = n0 >> 10;
    const float* gbias = a.bias[EPI == 0 ? gate : 0];
#pragma unroll
    for (int mt = 0; mt < 4; mt++) {
#pragma unroll
        for (int nt = 0; nt < 4; nt++) {
            const int row0 = m0 + mw + mt * 16 + q;
            const int col  = n0 + nw + nt * 8 + 2 * r;
#pragma unroll
            for (int h = 0; h < 2; h++) {   // rows q and q+8
                const int row = row0 + h * 8;
                float x0 = acc[mt][nt][2 * h + 0];
                float x1 = acc[mt][nt][2 * h + 1];
                if (EPI == 0) {
                    x0 += gbias[col & 1023];
                    x1 += gbias[(col + 1) & 1023];
                    if (gate < 3) {
                        x0 = 1.0f / (1.0f + __expf(-x0));
                        x1 = 1.0f / (1.0f + __expf(-x1));
                    } else {
                        x0 = tanhf(x0);
                        x1 = tanhf(x1);
                    }
                } else if (EPI == 1) {
                    x0 += a.bias[0][col]     + a.bias[1][col]     + a.add[(size_t)row * 1024 + col];
                    x1 += a.bias[0][col + 1] + a.bias[1][col + 1] + a.add[(size_t)row * 1024 + col + 1];
                } else {
                    x0 += gbias[col];
                    x1 += gbias[col + 1];
                }
                *(float2*)(a.out + (size_t)row * a.Nout + col) = make_float2(x0, x1);
            }
        }
    }
}

__global__ void lstm_pointwise(const float* __restrict__ gates,
                               const float* __restrict__ prev_cell,
                               float* __restrict__ hidden,
                               float* __restrict__ cell)
{
    const int idx = blockIdx.x * blockDim.x + threadIdx.x;
    if (idx >= 4096 * 1024) return;
    const int m = idx >> 10;
    const int h = idx & 1023;
    const float* gr = gates + (size_t)m * 4096;
    const float i = gr[h];
    const float f = gr[1024 + h];
    const float o = gr[2048 + h];
    const float g = gr[3072 + h];
    const float c = f * prev_cell[idx] + i * g;
    cell[idx] = c;
    hidden[idx] = o * tanhf(c);
}

extern "C" void kernel_launch(void* const* d_in, const int* in_sizes, int n_in,
                              void* d_out, int out_size)
{
    const float* emb = (const float*)d_in[0];
    const float* hid = (const float*)d_in[1];
    const float* pc  = (const float*)d_in[2];
    const float* ctx = (const float*)d_in[3];
    const float* Wi = (const float*)d_in[4];  const float* bi = (const float*)d_in[5];
    const float* Wf = (const float*)d_in[6];  const float* bf = (const float*)d_in[7];
    const float* Wo = (const float*)d_in[8];  const float* bo = (const float*)d_in[9];
    const float* Wg = (const float*)d_in[10]; const float* bg = (const float*)d_in[11];
    const float* Wc = (const float*)d_in[12]; const float* bc = (const float*)d_in[13];
    const float* Wh = (const float*)d_in[14]; const float* bh = (const float*)d_in[15];
    const float* Wp = (const float*)d_in[16]; const float* bp = (const float*)d_in[17];

    const int B = 4096, E = 1024, H = 1024;
    float* out    = (float*)d_out;
    float* pred   = out;
    float* hidden = out + (size_t)B * E;
    float* cell   = out + (size_t)B * E + (size_t)B * H;

    float* gates = nullptr; float* resid = nullptr;
    cudaGetSymbolAddress((void**)&gates, g_gates);
    cudaGetSymbolAddress((void**)&resid, g_resid);

    cudaFuncSetAttribute(gemm_mma<0>, cudaFuncAttributeMaxDynamicSharedMemorySize, SMEM_BYTES);
    cudaFuncSetAttribute(gemm_mma<1>, cudaFuncAttributeMaxDynamicSharedMemorySize, SMEM_BYTES);
    cudaFuncSetAttribute(gemm_mma<2>, cudaFuncAttributeMaxDynamicSharedMemorySize, SMEM_BYTES);

    // Stage 1: gates = act(concat @ [Wi;Wf;Wo;Wg]^T + b)   M=4096 N=4096 K=3072
    {
        TArgs a = {};
        a.aseg[0] = emb; a.aseg[1] = hid; a.aseg[2] = ctx;
        a.w[0] = Wi; a.w[1] = Wf; a.w[2] = Wo; a.w[3] = Wg;
        a.bias[0] = bi; a.bias[1] = bf; a.bias[2] = bo; a.bias[3] = bg;
        a.out = gates; a.K = 3072; a.Nout = 4096; a.wn_mode = 1;
        gemm_mma<0><<<dim3(32, 32), 256, SMEM_BYTES>>>(a);
    }
    // Stage 2: pointwise
    lstm_pointwise<<<(B * H + 255) / 256, 256>>>(gates, pc, hidden, cell);
    // Stage 3: resid = emb + hidden@Wh^T + bh + ctx@Wc^T + bc   M=4096 N=1024 K=2048
    {
        TArgs a = {};
        a.aseg[0] = hidden; a.aseg[1] = ctx;
        a.w[0] = Wh; a.w[1] = Wc;
        a.bias[0] = bh; a.bias[1] = bc;
        a.add = emb;
        a.out = resid; a.K = 2048; a.Nout = 1024; a.wn_mode = 0;
        gemm_mma<1><<<dim3(32, 8), 256, SMEM_BYTES>>>(a);
    }
    // Stage 4: pred = resid@Wp^T + bp   M=4096 N=1024 K=1024
    {
        TArgs a = {};
        a.aseg[0] = resid;
        a.w[0] = Wp;
        a.bias[0] = bp;
        a.out = pred; a.K = 1024; a.Nout = 1024; a.wn_mode = 0;
        gemm_mma<2><<<dim3(32, 8), 256, SMEM_BYTES>>>(a);
    }
}

// round 4
// speedup vs baseline: 3.2572x; 1.6157x over previous
#include <cuda_runtime.h>
#include <cstdint>
#include <math.h>

// ---------------------------------------------------------------------------
// LSTM_80831284510999 — round 3: mma.sync tf32, 512 threads (16 warps),
// CTA tile 128x256, cp.async double-buffered staging, cvt.rna in frag path.
// ---------------------------------------------------------------------------

static constexpr int ROWPAD = 36;            // padded row (floats): conflict-free frag reads
static constexpr int A_FLOATS = 128 * ROWPAD;   // 4608
static constexpr int B_FLOATS = 256 * ROWPAD;   // 9216
static constexpr int SMEM_BYTES = (2 * A_FLOATS + 2 * B_FLOATS) * 4;  // 110592

__device__ float g_gates[4096ull * 4096ull];
__device__ float g_resid[4096ull * 1024ull];

__device__ __forceinline__ uint32_t smem_u32(const void* p) {
    uint32_t a;
    asm("{ .reg .u64 t; cvta.to.shared.u64 t, %1; cvt.u32.u64 %0, t; }" : "=r"(a) : "l"(p));
    return a;
}
__device__ __forceinline__ uint32_t f2tf32_u(float x) {
    uint32_t u; asm("cvt.rna.tf32.f32 %0, %1;" : "=r"(u) : "f"(x)); return u;
}
__device__ __forceinline__ void cp_async16(uint32_t saddr, const void* g) {
    asm volatile("cp.async.cg.shared.global [%0], [%1], 16;" :: "r"(saddr), "l"(g) : "memory");
}
__device__ __forceinline__ void cp_commit() {
    asm volatile("cp.async.commit_group;" ::: "memory");
}
template <int N> __device__ __forceinline__ void cp_wait() {
    asm volatile("cp.async.wait_group %0;" :: "n"(N) : "memory");
}

struct TArgs {
    const float* aseg[3];   // A K-segments, each [4096, 1024] row-major
    const float* w[4];      // W segments
    const float* bias[4];
    const float* add;       // optional [M,1024] addend (EPI 1)
    float* out;
    int K;
    int Nout;
    int wn_mode;            // 1: W seg by gate (row stride 3072), 0: by kseg (stride 1024)
};

// EPI 0: gates (bias + sigmoid/sigmoid/sigmoid/tanh by n>>10)
// EPI 1: + bias0[n] + bias1[n] + add[m,n]
// EPI 2: + bias0[n]
template <int EPI>
__global__ void __launch_bounds__(512, 1) gemm_mma(TArgs a)
{
    extern __shared__ float sm[];
    const uint32_t sbase = smem_u32(sm);

    const int tid  = threadIdx.x;
    const int m0   = blockIdx.x * 128;
    const int n0   = blockIdx.y * 256;
    const int wid  = tid >> 5, lane = tid & 31;
    const int mw   = (wid >> 3) * 64;      // 2 m-groups
    const int nw   = (wid & 7) * 32;       // 8 n-groups
    const int q    = lane >> 2, r = lane & 3;
    const int NC   = a.K >> 5;

    float acc[4][4][4];
#pragma unroll
    for (int i = 0; i < 4; i++)
#pragma unroll
        for (int j = 0; j < 4; j++)
#pragma unroll
            for (int e = 0; e < 4; e++) acc[i][j][e] = 0.0f;

    auto issue_chunk = [&](int c, int b) {
        const int k0 = c * 32;
        const float* ab = a.aseg[k0 >> 10] + (size_t)m0 * 1024 + (k0 & 1023);
        const float* wb; size_t ws;
        if (a.wn_mode) { wb = a.w[n0 >> 10] + (size_t)(n0 & 1023) * 3072 + k0; ws = 3072; }
        else           { wb = a.w[k0 >> 10] + (size_t)n0 * 1024 + (k0 & 1023); ws = 1024; }
        const uint32_t Ab = sbase + (uint32_t)(b * A_FLOATS) * 4;
        const uint32_t Bb = sbase + (uint32_t)(2 * A_FLOATS + b * B_FLOATS) * 4;
#pragma unroll
        for (int t = 0; t < 2; t++) {
            const int id = tid + t * 512;
            const int m = id >> 3, kq = id & 7;
            cp_async16(Ab + (uint32_t)(m * ROWPAD + kq * 4) * 4, ab + (size_t)m * 1024 + kq * 4);
        }
#pragma unroll
        for (int t = 0; t < 4; t++) {
            const int id = tid + t * 512;
            const int m = id >> 3, kq = id & 7;
            cp_async16(Bb + (uint32_t)(m * ROWPAD + kq * 4) * 4, wb + (size_t)m * ws + kq * 4);
        }
        cp_commit();
    };

    auto mma_chunk = [&](int b) {
        const float* A = sm + b * A_FLOATS;
        const float* B = sm + 2 * A_FLOATS + b * B_FLOATS;
#pragma unroll
        for (int kk = 0; kk < 32; kk += 8) {
            uint32_t af[4][4], bf[4][2];
#pragma unroll
            for (int mt = 0; mt < 4; mt++) {
                const int base = (mw + mt * 16 + q) * ROWPAD + kk + r;
                af[mt][0] = f2tf32_u(A[base]);
                af[mt][1] = f2tf32_u(A[base + 8 * ROWPAD]);
                af[mt][2] = f2tf32_u(A[base + 4]);
                af[mt][3] = f2tf32_u(A[base + 8 * ROWPAD + 4]);
            }
#pragma unroll
            for (int nt = 0; nt < 4; nt++) {
                const int base = (nw + nt * 8 + q) * ROWPAD + kk + r;
                bf[nt][0] = f2tf32_u(B[base]);
                bf[nt][1] = f2tf32_u(B[base + 4]);
            }
#pragma unroll
            for (int mt = 0; mt < 4; mt++)
#pragma unroll
                for (int nt = 0; nt < 4; nt++) {
                    asm volatile(
                        "mma.sync.aligned.m16n8k8.row.col.f32.tf32.tf32.f32 "
                        "{%0,%1,%2,%3}, {%4,%5,%6,%7}, {%8,%9}, {%0,%1,%2,%3};"
                        : "+f"(acc[mt][nt][0]), "+f"(acc[mt][nt][1]),
                          "+f"(acc[mt][nt][2]), "+f"(acc[mt][nt][3])
                        : "r"(af[mt][0]), "r"(af[mt][1]), "r"(af[mt][2]), "r"(af[mt][3]),
                          "r"(bf[nt][0]), "r"(bf[nt][1]));
                }
        }
    };

    issue_chunk(0, 0);
    for (int c = 0; c < NC; c++) {
        if (c + 1 < NC) { issue_chunk(c + 1, (c + 1) & 1); cp_wait<1>(); }
        else            { cp_wait<0>(); }
        __syncthreads();
        mma_chunk(c & 1);
        __syncthreads();   // all reads of this buffer done before next-next overwrite
    }

    // ---- epilogue: fused bias/activation, direct from register accumulators ----
    const int gate = n0 >> 10;
    const float* gbias = a.bias[EPI == 0 ? gate : 0];
#pragma unroll
    for (int mt = 0; mt < 4; mt++) {
#pragma unroll
        for (int nt = 0; nt < 4; nt++) {
            const int row0 = m0 + mw + mt * 16 + q;
            const int col  = n0 + nw + nt * 8 + 2 * r;
#pragma unroll
            for (int h = 0; h < 2; h++) {
                const int row = row0 + h * 8;
                float x0 = acc[mt][nt][2 * h + 0];
                float x1 = acc[mt][nt][2 * h + 1];
                if (EPI == 0) {
                    x0 += gbias[col & 1023];
                    x1 += gbias[(col + 1) & 1023];
                    if (gate < 3) {
                        x0 = 1.0f / (1.0f + __expf(-x0));
                        x1 = 1.0f / (1.0f + __expf(-x1));
                    } else {
                        x0 = tanhf(x0);
                        x1 = tanhf(x1);
                    }
                } else if (EPI == 1) {
                    x0 += a.bias[0][col]     + a.bias[1][col]     + a.add[(size_t)row * 1024 + col];
                    x1 += a.bias[0][col + 1] + a.bias[1][col + 1] + a.add[(size_t)row * 1024 + col + 1];
                } else {
                    x0 += gbias[col];
                    x1 += gbias[col + 1];
                }
                *(float2*)(a.out + (size_t)row * a.Nout + col) = make_float2(x0, x1);
            }
        }
    }
}

__global__ void lstm_pointwise(const float4* __restrict__ gates,
                               const float4* __restrict__ prev_cell,
                               float4* __restrict__ hidden,
                               float4* __restrict__ cell)
{
    const int idx = blockIdx.x * blockDim.x + threadIdx.x;   // over float4s
    if (idx >= 4096 * 256) return;
    const int m = idx >> 8;
    const int h4 = idx & 255;
    const float4 gi = gates[m * 1024 + h4];
    const float4 gf = gates[m * 1024 + 256 + h4];
    const float4 go = gates[m * 1024 + 512 + h4];
    const float4 gg = gates[m * 1024 + 768 + h4];
    const float4 pc = prev_cell[idx];
    float4 c, hd;
    c.x = gf.x * pc.x + gi.x * gg.x;  hd.x = go.x * tanhf(c.x);
    c.y = gf.y * pc.y + gi.y * gg.y;  hd.y = go.y * tanhf(c.y);
    c.z = gf.z * pc.z + gi.z * gg.z;  hd.z = go.z * tanhf(c.z);
    c.w = gf.w * pc.w + gi.w * gg.w;  hd.w = go.w * tanhf(c.w);
    cell[idx] = c;
    hidden[idx] = hd;
}

extern "C" void kernel_launch(void* const* d_in, const int* in_sizes, int n_in,
                              void* d_out, int out_size)
{
    const float* emb = (const float*)d_in[0];
    const float* hid = (const float*)d_in[1];
    const float* pc  = (const float*)d_in[2];
    const float* ctx = (const float*)d_in[3];
    const float* Wi = (const float*)d_in[4];  const float* bi = (const float*)d_in[5];
    const float* Wf = (const float*)d_in[6];  const float* bf = (const float*)d_in[7];
    const float* Wo = (const float*)d_in[8];  const float* bo = (const float*)d_in[9];
    const float* Wg = (const float*)d_in[10]; const float* bg = (const float*)d_in[11];
    const float* Wc = (const float*)d_in[12]; const float* bc = (const float*)d_in[13];
    const float* Wh = (const float*)d_in[14]; const float* bh = (const float*)d_in[15];
    const float* Wp = (const float*)d_in[16]; const float* bp = (const float*)d_in[17];

    const int B = 4096, E = 1024, H = 1024;
    float* out    = (float*)d_out;
    float* pred   = out;
    float* hidden = out + (size_t)B * E;
    float* cell   = out + (size_t)B * E + (size_t)B * H;

    float* gates = nullptr; float* resid = nullptr;
    cudaGetSymbolAddress((void**)&gates, g_gates);
    cudaGetSymbolAddress((void**)&resid, g_resid);

    cudaFuncSetAttribute(gemm_mma<0>, cudaFuncAttributeMaxDynamicSharedMemorySize, SMEM_BYTES);
    cudaFuncSetAttribute(gemm_mma<1>, cudaFuncAttributeMaxDynamicSharedMemorySize, SMEM_BYTES);
    cudaFuncSetAttribute(gemm_mma<2>, cudaFuncAttributeMaxDynamicSharedMemorySize, SMEM_BYTES);

    // Stage 1: gates = act(concat @ [Wi;Wf;Wo;Wg]^T + b)   M=4096 N=4096 K=3072
    {
        TArgs a = {};
        a.aseg[0] = emb; a.aseg[1] = hid; a.aseg[2] = ctx;
        a.w[0] = Wi; a.w[1] = Wf; a.w[2] = Wo; a.w[3] = Wg;
        a.bias[0] = bi; a.bias[1] = bf; a.bias[2] = bo; a.bias[3] = bg;
        a.out = gates; a.K = 3072; a.Nout = 4096; a.wn_mode = 1;
        gemm_mma<0><<<dim3(32, 16), 512, SMEM_BYTES>>>(a);
    }
    // Stage 2: pointwise
    lstm_pointwise<<<4096, 256>>>((const float4*)gates, (const float4*)pc,
                                  (float4*)hidden, (float4*)cell);
    // Stage 3: resid = emb + hidden@Wh^T + bh + ctx@Wc^T + bc   M=4096 N=1024 K=2048
    {
        TArgs a = {};
        a.aseg[0] = hidden; a.aseg[1] = ctx;
        a.w[0] = Wh; a.w[1] = Wc;
        a.bias[0] = bh; a.bias[1] = bc;
        a.add = emb;
        a.out = resid; a.K = 2048; a.Nout = 1024; a.wn_mode = 0;
        gemm_mma<1><<<dim3(32, 4), 512, SMEM_BYTES>>>(a);
    }
    // Stage 4: pred = resid@Wp^T + bp   M=4096 N=1024 K=1024
    {
        TArgs a = {};
        a.aseg[0] = resid;
        a.w[0] = Wp;
        a.bias[0] = bp;
        a.out = pred; a.K = 1024; a.Nout = 1024; a.wn_mode = 0;
        gemm_mma<2><<<dim3(32, 4), 512, SMEM_BYTES>>>(a);
    }
}

// round 5
// speedup vs baseline: 3.5950x; 1.1037x over previous
#include <cuda_runtime.h>
#include <cstdint>
#include <math.h>

// ---------------------------------------------------------------------------
// LSTM_80831284510999 — round 4: mma.sync tf32, pre-rounded operands (zero cvt
// in mainloop), 256 threads, warp tile 64x64, CTA tile 128x256, cp.async
// double-buffered. Generic C[M,N] = A[M,K] @ B[N,K]^T, fused epilogues.
// ---------------------------------------------------------------------------

static constexpr int ROWPAD = 36;
static constexpr int A_FLOATS = 128 * ROWPAD;
static constexpr int B_FLOATS = 256 * ROWPAD;
static constexpr int SMEM_BYTES = (2 * A_FLOATS + 2 * B_FLOATS) * 4;  // 110592

// Scratch (allocation-free rule)
__device__ float g_A1[4096ull * 3072ull];    // rounded concat(emb,hid,ctx)
__device__ float g_W1[4096ull * 3072ull];    // rounded [Wi;Wf;Wo;Wg]
__device__ float g_gates[4096ull * 4096ull];
__device__ float g_A3[4096ull * 2048ull];    // rounded [hidden, ctx]
__device__ float g_W3[1024ull * 2048ull];    // rounded [Wh | Wc]
__device__ float g_Wp[1024ull * 1024ull];    // rounded Wp
__device__ float g_resid[4096ull * 1024ull]; // rounded resid
__device__ float g_bias_hc[1024];            // bh + bc

__device__ __forceinline__ uint32_t smem_u32(const void* p) {
    uint32_t a;
    asm("{ .reg .u64 t; cvta.to.shared.u64 t, %1; cvt.u32.u64 %0, t; }" : "=r"(a) : "l"(p));
    return a;
}
__device__ __forceinline__ float f2tf32(float x) {
    uint32_t u; asm("cvt.rna.tf32.f32 %0, %1;" : "=r"(u) : "f"(x));
    return __uint_as_float(u);
}
__device__ __forceinline__ float4 rna4(float4 v) {
    return make_float4(f2tf32(v.x), f2tf32(v.y), f2tf32(v.z), f2tf32(v.w));
}
__device__ __forceinline__ void cp_async16(uint32_t saddr, const void* g) {
    asm volatile("cp.async.cg.shared.global [%0], [%1], 16;" :: "r"(saddr), "l"(g) : "memory");
}
__device__ __forceinline__ void cp_commit() {
    asm volatile("cp.async.commit_group;" ::: "memory");
}
template <int N> __device__ __forceinline__ void cp_wait() {
    asm volatile("cp.async.wait_group %0;" :: "n"(N) : "memory");
}

struct GArgs {
    const float* A;        // [M, K] rounded, row-major
    const float* B;        // [N, K] rounded, row-major
    const float* bias[4];
    const float* add;      // EPI 1 addend [M,1024]
    float* out;
    int K;
    int Nout;
};

// EPI 0: gates (bias[gate] + sigmoid/sigmoid/sigmoid/tanh, gate = n0>>10)
// EPI 1: round(acc + bias0[n] + add[m,n])   (resid; consumed only by MMA)
// EPI 2: acc + bias0[n]
template <int EPI>
__global__ void __launch_bounds__(256, 1) gemm_mma(GArgs a)
{
    extern __shared__ float sm[];
    const uint32_t sbase = smem_u32(sm);

    const int tid  = threadIdx.x;
    const int m0   = blockIdx.x * 128;
    const int n0   = blockIdx.y * 256;
    const int wid  = tid >> 5, lane = tid & 31;
    const int mw   = (wid >> 2) * 64;      // 2 m-groups of 64
    const int nw   = (wid & 3) * 64;       // 4 n-groups of 64
    const int q    = lane >> 2, r = lane & 3;
    const int NC   = a.K >> 5;

    float acc[4][8][4];
#pragma unroll
    for (int i = 0; i < 4; i++)
#pragma unroll
        for (int j = 0; j < 8; j++)
#pragma unroll
            for (int e = 0; e < 4; e++) acc[i][j][e] = 0.0f;

    auto issue_chunk = [&](int c, int b) {
        const int k0 = c * 32;
        const float* ab = a.A + (size_t)m0 * a.K + k0;
        const float* wb = a.B + (size_t)n0 * a.K + k0;
        const uint32_t Ab = sbase + (uint32_t)(b * A_FLOATS) * 4;
        const uint32_t Bb = sbase + (uint32_t)(2 * A_FLOATS + b * B_FLOATS) * 4;
#pragma unroll
        for (int t = 0; t < 4; t++) {
            const int id = tid + t * 256;
            const int m = id >> 3, kq = id & 7;
            cp_async16(Ab + (uint32_t)(m * ROWPAD + kq * 4) * 4, ab + (size_t)m * a.K + kq * 4);
        }
#pragma unroll
        for (int t = 0; t < 8; t++) {
            const int id = tid + t * 256;
            const int m = id >> 3, kq = id & 7;
            cp_async16(Bb + (uint32_t)(m * ROWPAD + kq * 4) * 4, wb + (size_t)m * a.K + kq * 4);
        }
        cp_commit();
    };

    auto mma_chunk = [&](int b) {
        const float* A = sm + b * A_FLOATS;
        const float* B = sm + 2 * A_FLOATS + b * B_FLOATS;
#pragma unroll
        for (int kk = 0; kk < 32; kk += 8) {
            uint32_t af[4][4], bf[8][2];
#pragma unroll
            for (int mt = 0; mt < 4; mt++) {
                const int base = (mw + mt * 16 + q) * ROWPAD + kk + r;
                af[mt][0] = __float_as_uint(A[base]);
                af[mt][1] = __float_as_uint(A[base + 8 * ROWPAD]);
                af[mt][2] = __float_as_uint(A[base + 4]);
                af[mt][3] = __float_as_uint(A[base + 8 * ROWPAD + 4]);
            }
#pragma unroll
            for (int nt = 0; nt < 8; nt++) {
                const int base = (nw + nt * 8 + q) * ROWPAD + kk + r;
                bf[nt][0] = __float_as_uint(B[base]);
                bf[nt][1] = __float_as_uint(B[base + 4]);
            }
#pragma unroll
            for (int mt = 0; mt < 4; mt++)
#pragma unroll
                for (int nt = 0; nt < 8; nt++) {
                    asm volatile(
                        "mma.sync.aligned.m16n8k8.row.col.f32.tf32.tf32.f32 "
                        "{%0,%1,%2,%3}, {%4,%5,%6,%7}, {%8,%9}, {%0,%1,%2,%3};"
                        : "+f"(acc[mt][nt][0]), "+f"(acc[mt][nt][1]),
                          "+f"(acc[mt][nt][2]), "+f"(acc[mt][nt][3])
                        : "r"(af[mt][0]), "r"(af[mt][1]), "r"(af[mt][2]), "r"(af[mt][3]),
                          "r"(bf[nt][0]), "r"(bf[nt][1]));
                }
        }
    };

    issue_chunk(0, 0);
    for (int c = 0; c < NC; c++) {
        if (c + 1 < NC) { issue_chunk(c + 1, (c + 1) & 1); cp_wait<1>(); }
        else            { cp_wait<0>(); }
        __syncthreads();
        mma_chunk(c & 1);
        __syncthreads();
    }

    // ---- fused epilogue from register accumulators ----
    const int gate = n0 >> 10;
    const float* gbias = a.bias[EPI == 0 ? gate : 0];
#pragma unroll
    for (int mt = 0; mt < 4; mt++) {
#pragma unroll
        for (int nt = 0; nt < 8; nt++) {
            const int row0 = m0 + mw + mt * 16 + q;
            const int col  = n0 + nw + nt * 8 + 2 * r;
#pragma unroll
            for (int h = 0; h < 2; h++) {
                const int row = row0 + h * 8;
                float x0 = acc[mt][nt][2 * h + 0];
                float x1 = acc[mt][nt][2 * h + 1];
                if (EPI == 0) {
                    x0 += gbias[col & 1023];
                    x1 += gbias[(col + 1) & 1023];
                    if (gate < 3) {
                        x0 = 1.0f / (1.0f + __expf(-x0));
                        x1 = 1.0f / (1.0f + __expf(-x1));
                    } else {
                        x0 = tanhf(x0);
                        x1 = tanhf(x1);
                    }
                } else if (EPI == 1) {
                    x0 = f2tf32(x0 + gbias[col]     + a.add[(size_t)row * 1024 + col]);
                    x1 = f2tf32(x1 + gbias[col + 1] + a.add[(size_t)row * 1024 + col + 1]);
                } else {
                    x0 += gbias[col];
                    x1 += gbias[col + 1];
                }
                *(float2*)(a.out + (size_t)row * a.Nout + col) = make_float2(x0, x1);
            }
        }
    }
}

// ---------------- pre-round / pointwise kernels ----------------

// Build g_A1 (rounded concat) and the ctx part of g_A3.
__global__ void prep_A1(const float4* __restrict__ emb, const float4* __restrict__ hid,
                        const float4* __restrict__ ctx)
{
    const int idx = blockIdx.x * blockDim.x + threadIdx.x;   // [4096 x 768] float4
    if (idx >= 4096 * 768) return;
    const int m = idx / 768, c4 = idx % 768;
    float4 v;
    if (c4 < 256)      v = emb[m * 256 + c4];
    else if (c4 < 512) v = hid[m * 256 + (c4 - 256)];
    else               v = ctx[m * 256 + (c4 - 512)];
    v = rna4(v);
    ((float4*)g_A1)[idx] = v;
    if (c4 >= 512)     // ctx also forms g_A3[:, 1024:2048]
        ((float4*)g_A3)[m * 512 + 256 + (c4 - 512)] = v;
}

__global__ void prep_W1(const float4* __restrict__ Wi, const float4* __restrict__ Wf,
                        const float4* __restrict__ Wo, const float4* __restrict__ Wg)
{
    const int idx = blockIdx.x * blockDim.x + threadIdx.x;   // [4096 x 768] float4
    if (idx >= 4096 * 768) return;
    const int n = idx / 768, c4 = idx % 768;
    const int gate = n >> 10, h = n & 1023;
    const float4* W = (gate == 0) ? Wi : (gate == 1) ? Wf : (gate == 2) ? Wo : Wg;
    ((float4*)g_W1)[idx] = rna4(W[h * 768 + c4]);
}

__global__ void prep_W3(const float4* __restrict__ Wh, const float4* __restrict__ Wc,
                        const float* __restrict__ bh, const float* __restrict__ bc)
{
    const int idx = blockIdx.x * blockDim.x + threadIdx.x;   // [1024 x 512] float4
    if (idx < 1024) g_bias_hc[idx] = bh[idx] + bc[idx];
    if (idx >= 1024 * 512) return;
    const int n = idx / 512, c4 = idx % 512;
    float4 v = (c4 < 256) ? Wh[n * 256 + c4] : Wc[n * 256 + (c4 - 256)];
    ((float4*)g_W3)[idx] = rna4(v);
}

__global__ void prep_Wp(const float4* __restrict__ Wp)
{
    const int idx = blockIdx.x * blockDim.x + threadIdx.x;   // [1024 x 256] float4
    if (idx >= 1024 * 256) return;
    ((float4*)g_Wp)[idx] = rna4(Wp[idx]);
}

__global__ void lstm_pointwise(const float4* __restrict__ gates,
                               const float4* __restrict__ prev_cell,
                               float4* __restrict__ hidden,
                               float4* __restrict__ cell)
{
    const int idx = blockIdx.x * blockDim.x + threadIdx.x;   // over float4
    if (idx >= 4096 * 256) return;
    const int m = idx >> 8, h4 = idx & 255;
    const float4 gi = gates[m * 1024 + h4];
    const float4 gf = gates[m * 1024 + 256 + h4];
    const float4 go = gates[m * 1024 + 512 + h4];
    const float4 gg = gates[m * 1024 + 768 + h4];
    const float4 pc = prev_cell[idx];
    float4 c, hd;
    c.x = gf.x * pc.x + gi.x * gg.x;  hd.x = go.x * tanhf(c.x);
    c.y = gf.y * pc.y + gi.y * gg.y;  hd.y = go.y * tanhf(c.y);
    c.z = gf.z * pc.z + gi.z * gg.z;  hd.z = go.z * tanhf(c.z);
    c.w = gf.w * pc.w + gi.w * gg.w;  hd.w = go.w * tanhf(c.w);
    cell[idx] = c;
    hidden[idx] = hd;
    ((float4*)g_A3)[m * 512 + h4] = rna4(hd);   // rounded hidden -> stage-3 A
}

extern "C" void kernel_launch(void* const* d_in, const int* in_sizes, int n_in,
                              void* d_out, int out_size)
{
    const float* emb = (const float*)d_in[0];
    const float* hid = (const float*)d_in[1];
    const float* pc  = (const float*)d_in[2];
    const float* ctx = (const float*)d_in[3];
    const float* Wi = (const float*)d_in[4];  const float* bi = (const float*)d_in[5];
    const float* Wf = (const float*)d_in[6];  const float* bf = (const float*)d_in[7];
    const float* Wo = (const float*)d_in[8];  const float* bo = (const float*)d_in[9];
    const float* Wg = (const float*)d_in[10]; const float* bg = (const float*)d_in[11];
    const float* Wc = (const float*)d_in[12]; const float* bc = (const float*)d_in[13];
    const float* Wh = (const float*)d_in[14]; const float* bh = (const float*)d_in[15];
    const float* Wp = (const float*)d_in[16]; const float* bp = (const float*)d_in[17];

    const int B = 4096, E = 1024, H = 1024;
    float* out    = (float*)d_out;
    float* pred   = out;
    float* hidden = out + (size_t)B * E;
    float* cell   = out + (size_t)B * E + (size_t)B * H;

    float *A1, *W1, *gates, *A3, *W3, *Wpr, *resid, *bias_hc;
    cudaGetSymbolAddress((void**)&A1, g_A1);
    cudaGetSymbolAddress((void**)&W1, g_W1);
    cudaGetSymbolAddress((void**)&gates, g_gates);
    cudaGetSymbolAddress((void**)&A3, g_A3);
    cudaGetSymbolAddress((void**)&W3, g_W3);
    cudaGetSymbolAddress((void**)&Wpr, g_Wp);
    cudaGetSymbolAddress((void**)&resid, g_resid);
    cudaGetSymbolAddress((void**)&bias_hc, g_bias_hc);

    cudaFuncSetAttribute(gemm_mma<0>, cudaFuncAttributeMaxDynamicSharedMemorySize, SMEM_BYTES);
    cudaFuncSetAttribute(gemm_mma<1>, cudaFuncAttributeMaxDynamicSharedMemorySize, SMEM_BYTES);
    cudaFuncSetAttribute(gemm_mma<2>, cudaFuncAttributeMaxDynamicSharedMemorySize, SMEM_BYTES);

    // Pre-round passes
    prep_A1<<<(4096 * 768 + 255) / 256, 256>>>((const float4*)emb, (const float4*)hid,
                                               (const float4*)ctx);
    prep_W1<<<(4096 * 768 + 255) / 256, 256>>>((const float4*)Wi, (const float4*)Wf,
                                               (const float4*)Wo, (const float4*)Wg);
    prep_W3<<<(1024 * 512 + 255) / 256, 256>>>((const float4*)Wh, (const float4*)Wc, bh, bc);
    prep_Wp<<<(1024 * 256 + 255) / 256, 256>>>((const float4*)Wp);

    // Stage 1: gates = act(A1 @ W1^T + b)   M=4096 N=4096 K=3072
    {
        GArgs a = {};
        a.A = A1; a.B = W1;
        a.bias[0] = bi; a.bias[1] = bf; a.bias[2] = bo; a.bias[3] = bg;
        a.out = gates; a.K = 3072; a.Nout = 4096;
        gemm_mma<0><<<dim3(32, 16), 256, SMEM_BYTES>>>(a);
    }
    // Stage 2: pointwise (also emits rounded hidden into A3)
    lstm_pointwise<<<4096, 256>>>((const float4*)gates, (const float4*)pc,
                                  (float4*)hidden, (float4*)cell);
    // Stage 3: resid = round(emb + A3 @ W3^T + bias_hc)   M=4096 N=1024 K=2048
    {
        GArgs a = {};
        a.A = A3; a.B = W3;
        a.bias[0] = bias_hc;
        a.add = emb;
        a.out = resid; a.K = 2048; a.Nout = 1024;
        gemm_mma<1><<<dim3(32, 4), 256, SMEM_BYTES>>>(a);
    }
    // Stage 4: pred = resid @ Wp^T + bp   M=4096 N=1024 K=1024
    {
        GArgs a = {};
        a.A = resid; a.B = Wpr;
        a.bias[0] = bp;
        a.out = pred; a.K = 1024; a.Nout = 1024;
        gemm_mma<2><<<dim3(32, 4), 256, SMEM_BYTES>>>(a);
    }
}

// round 10
// speedup vs baseline: 6.3141x; 1.7564x over previous
#include <cuda_runtime.h>
#include <cuda_fp16.h>
#include <cstdint>
#include <math.h>

// ---------------------------------------------------------------------------
// LSTM_80831284510999 — round 9 (= round 5 kernel; broker timed out 4x):
// fp16 mma.sync m16n8k16 (same 10-bit mantissa as tf32, 2x throughput, half
// the operand traffic). Pre-converted half operands, CTA tile 128x256, warp
// tile 64x64, BK=64, cp.async double-buffer.
// ---------------------------------------------------------------------------

static constexpr int ROWP = 36;                 // half2 per padded row (32 data + 4 pad)
static constexpr int A_H2 = 128 * ROWP;         // 4608 half2 = 18 KB
static constexpr int B_H2 = 256 * ROWP;         // 9216 half2 = 36 KB
static constexpr int SMEM_BYTES = (2 * A_H2 + 2 * B_H2) * 4;   // 110592 B

// Scratch (allocation-free rule)
__device__ __half g_A1[4096ull * 3072ull];    // concat(emb,hid,ctx) as fp16
__device__ __half g_W1[4096ull * 3072ull];    // [Wi;Wf;Wo;Wg] as fp16
__device__ float  g_gates[4096ull * 4096ull];
__device__ __half g_A3[4096ull * 2048ull];    // [hidden, ctx] as fp16
__device__ __half g_W3[1024ull * 2048ull];    // [Wh | Wc] as fp16
__device__ __half g_Wp[1024ull * 1024ull];    // Wp as fp16
__device__ __half g_resid[4096ull * 1024ull]; // resid as fp16
__device__ float  g_bias_hc[1024];            // bh + bc

__device__ __forceinline__ uint32_t smem_u32(const void* p) {
    uint32_t a;
    asm("{ .reg .u64 t; cvta.to.shared.u64 t, %1; cvt.u32.u64 %0, t; }" : "=r"(a) : "l"(p));
    return a;
}
__device__ __forceinline__ void cp_async16(uint32_t saddr, const void* g) {
    asm volatile("cp.async.cg.shared.global [%0], [%1], 16;" :: "r"(saddr), "l"(g) : "memory");
}
__device__ __forceinline__ void cp_commit() {
    asm volatile("cp.async.commit_group;" ::: "memory");
}
template <int N> __device__ __forceinline__ void cp_wait() {
    asm volatile("cp.async.wait_group %0;" :: "n"(N) : "memory");
}

struct GArgs {
    const __half* A;       // [M, K] fp16 row-major
    const __half* B;       // [N, K] fp16 row-major
    const float* bias[4];
    const float* add;      // EPI 1 addend [M,1024] (f32)
    float* out;            // f32 out (EPI 0/2)
    __half* outh;          // half out (EPI 1)
    int K;
    int Nout;
};

// EPI 0: gates (bias[gate] + sigmoid/sigmoid/sigmoid/tanh, gate = n0>>10)
// EPI 1: half(acc + bias0[n] + add[m,n])  -> outh
// EPI 2: acc + bias0[n]                   -> out
template <int EPI>
__global__ void __launch_bounds__(256, 1) gemm_mma(GArgs a)
{
    extern __shared__ __half2 smh[];
    const uint32_t sbase = smem_u32(smh);

    const int tid  = threadIdx.x;
    const int m0   = blockIdx.x * 128;
    const int n0   = blockIdx.y * 256;
    const int wid  = tid >> 5, lane = tid & 31;
    const int mw   = (wid >> 2) * 64;      // 2 m-groups of 64
    const int nw   = (wid & 3) * 64;       // 4 n-groups of 64
    const int q    = lane >> 2, r = lane & 3;
    const int NC   = a.K >> 6;             // BK = 64

    float acc[4][8][4];
#pragma unroll
    for (int i = 0; i < 4; i++)
#pragma unroll
        for (int j = 0; j < 8; j++)
#pragma unroll
            for (int e = 0; e < 4; e++) acc[i][j][e] = 0.0f;

    auto issue_chunk = [&](int c, int b) {
        const int k0 = c * 64;
        const __half* ab = a.A + (size_t)m0 * a.K + k0;
        const __half* wb = a.B + (size_t)n0 * a.K + k0;
        const uint32_t Ab = sbase + (uint32_t)(b * A_H2) * 4;
        const uint32_t Bb = sbase + (uint32_t)(2 * A_H2 + b * B_H2) * 4;
#pragma unroll
        for (int t = 0; t < 4; t++) {       // A: 128 rows x 8 x 16B
            const int id = tid + t * 256;
            const int m = id >> 3, kq = id & 7;
            cp_async16(Ab + (uint32_t)(m * ROWP + kq * 4) * 4, ab + (size_t)m * a.K + kq * 8);
        }
#pragma unroll
        for (int t = 0; t < 8; t++) {       // B: 256 rows x 8 x 16B
            const int id = tid + t * 256;
            const int m = id >> 3, kq = id & 7;
            cp_async16(Bb + (uint32_t)(m * ROWP + kq * 4) * 4, wb + (size_t)m * a.K + kq * 8);
        }
        cp_commit();
    };

    auto mma_chunk = [&](int b) {
        const __half2* A = smh + b * A_H2;
        const __half2* B = smh + 2 * A_H2 + b * B_H2;
#pragma unroll
        for (int s = 0; s < 4; s++) {       // 4 k16 steps per BK=64 chunk
            const int kc = s * 8;           // half2 offset
            uint32_t af[4][4], bf[8][2];
#pragma unroll
            for (int mt = 0; mt < 4; mt++) {
                const int base = (mw + mt * 16 + q) * ROWP + kc + r;
                af[mt][0] = *(const uint32_t*)&A[base];
                af[mt][1] = *(const uint32_t*)&A[base + 8 * ROWP];
                af[mt][2] = *(const uint32_t*)&A[base + 4];
                af[mt][3] = *(const uint32_t*)&A[base + 8 * ROWP + 4];
            }
#pragma unroll
            for (int nt = 0; nt < 8; nt++) {
                const int base = (nw + nt * 8 + q) * ROWP + kc + r;
                bf[nt][0] = *(const uint32_t*)&B[base];
                bf[nt][1] = *(const uint32_t*)&B[base + 4];
            }
#pragma unroll
            for (int mt = 0; mt < 4; mt++)
#pragma unroll
                for (int nt = 0; nt < 8; nt++) {
                    asm volatile(
                        "mma.sync.aligned.m16n8k16.row.col.f32.f16.f16.f32 "
                        "{%0,%1,%2,%3}, {%4,%5,%6,%7}, {%8,%9}, {%0,%1,%2,%3};"
                        : "+f"(acc[mt][nt][0]), "+f"(acc[mt][nt][1]),
                          "+f"(acc[mt][nt][2]), "+f"(acc[mt][nt][3])
                        : "r"(af[mt][0]), "r"(af[mt][1]), "r"(af[mt][2]), "r"(af[mt][3]),
                          "r"(bf[nt][0]), "r"(bf[nt][1]));
                }
        }
    };

    issue_chunk(0, 0);
    for (int c = 0; c < NC; c++) {
        if (c + 1 < NC) { issue_chunk(c + 1, (c + 1) & 1); cp_wait<1>(); }
        else            { cp_wait<0>(); }
        __syncthreads();
        mma_chunk(c & 1);
        __syncthreads();
    }

    // ---- fused epilogue from register accumulators ----
    const int gate = n0 >> 10;
    const float* gbias = a.bias[EPI == 0 ? gate : 0];
#pragma unroll
    for (int mt = 0; mt < 4; mt++) {
#pragma unroll
        for (int nt = 0; nt < 8; nt++) {
            const int row0 = m0 + mw + mt * 16 + q;
            const int col  = n0 + nw + nt * 8 + 2 * r;
#pragma unroll
            for (int h = 0; h < 2; h++) {
                const int row = row0 + h * 8;
                float x0 = acc[mt][nt][2 * h + 0];
                float x1 = acc[mt][nt][2 * h + 1];
                if (EPI == 0) {
                    x0 += gbias[col & 1023];
                    x1 += gbias[(col + 1) & 1023];
                    if (gate < 3) {
                        x0 = 1.0f / (1.0f + __expf(-x0));
                        x1 = 1.0f / (1.0f + __expf(-x1));
                    } else {
                        x0 = tanhf(x0);
                        x1 = tanhf(x1);
                    }
                    *(float2*)(a.out + (size_t)row * a.Nout + col) = make_float2(x0, x1);
                } else if (EPI == 1) {
                    x0 += gbias[col]     + a.add[(size_t)row * 1024 + col];
                    x1 += gbias[col + 1] + a.add[(size_t)row * 1024 + col + 1];
                    *(__half2*)(a.outh + (size_t)row * a.Nout + col) = __floats2half2_rn(x0, x1);
                } else {
                    x0 += gbias[col];
                    x1 += gbias[col + 1];
                    *(float2*)(a.out + (size_t)row * a.Nout + col) = make_float2(x0, x1);
                }
            }
        }
    }
}

// ---------------- prep / pointwise kernels ----------------

__global__ void prep_A1(const float4* __restrict__ emb, const float4* __restrict__ hid,
                        const float4* __restrict__ ctx)
{
    const int idx = blockIdx.x * blockDim.x + threadIdx.x;   // [4096 x 768] float4
    if (idx >= 4096 * 768) return;
    const int m = idx / 768, c4 = idx % 768;
    float4 v;
    if (c4 < 256)      v = emb[m * 256 + c4];
    else if (c4 < 512) v = hid[m * 256 + (c4 - 256)];
    else               v = ctx[m * 256 + (c4 - 512)];
    const __half2 h0 = __floats2half2_rn(v.x, v.y);
    const __half2 h1 = __floats2half2_rn(v.z, v.w);
    __half2* out = (__half2*)g_A1;
    out[idx * 2] = h0; out[idx * 2 + 1] = h1;
    if (c4 >= 512) {    // ctx also forms g_A3[:, 1024:2048]
        __half2* a3 = (__half2*)g_A3;
        const int b = m * 1024 + 512 + (c4 - 512) * 2;
        a3[b] = h0; a3[b + 1] = h1;
    }
}

__global__ void prep_W1(const float4* __restrict__ Wi, const float4* __restrict__ Wf,
                        const float4* __restrict__ Wo, const float4* __restrict__ Wg)
{
    const int idx = blockIdx.x * blockDim.x + threadIdx.x;   // [4096 x 768] float4
    if (idx >= 4096 * 768) return;
    const int n = idx / 768, c4 = idx % 768;
    const int gate = n >> 10, h = n & 1023;
    const float4* W = (gate == 0) ? Wi : (gate == 1) ? Wf : (gate == 2) ? Wo : Wg;
    const float4 v = W[h * 768 + c4];
    __half2* out = (__half2*)g_W1;
    out[idx * 2]     = __floats2half2_rn(v.x, v.y);
    out[idx * 2 + 1] = __floats2half2_rn(v.z, v.w);
}

__global__ void prep_W3(const float4* __restrict__ Wh, const float4* __restrict__ Wc,
                        const float* __restrict__ bh, const float* __restrict__ bc)
{
    const int idx = blockIdx.x * blockDim.x + threadIdx.x;   // [1024 x 512] float4
    if (idx < 1024) g_bias_hc[idx] = bh[idx] + bc[idx];
    if (idx >= 1024 * 512) return;
    const int n = idx / 512, c4 = idx % 512;
    const float4 v = (c4 < 256) ? Wh[n * 256 + c4] : Wc[n * 256 + (c4 - 256)];
    __half2* out = (__half2*)g_W3;
    out[idx * 2]     = __floats2half2_rn(v.x, v.y);
    out[idx * 2 + 1] = __floats2half2_rn(v.z, v.w);
}

__global__ void prep_Wp(const float4* __restrict__ Wp)
{
    const int idx = blockIdx.x * blockDim.x + threadIdx.x;   // [1024 x 256] float4
    if (idx >= 1024 * 256) return;
    const float4 v = Wp[idx];
    __half2* out = (__half2*)g_Wp;
    out[idx * 2]     = __floats2half2_rn(v.x, v.y);
    out[idx * 2 + 1] = __floats2half2_rn(v.z, v.w);
}

__global__ void lstm_pointwise(const float4* __restrict__ gates,
                               const float4* __restrict__ prev_cell,
                               float4* __restrict__ hidden,
                               float4* __restrict__ cell)
{
    const int idx = blockIdx.x * blockDim.x + threadIdx.x;   // over float4
    if (idx >= 4096 * 256) return;
    const int m = idx >> 8, h4 = idx & 255;
    const float4 gi = gates[m * 1024 + h4];
    const float4 gf = gates[m * 1024 + 256 + h4];
    const float4 go = gates[m * 1024 + 512 + h4];
    const float4 gg = gates[m * 1024 + 768 + h4];
    const float4 pc = prev_cell[idx];
    float4 c, hd;
    c.x = gf.x * pc.x + gi.x * gg.x;  hd.x = go.x * tanhf(c.x);
    c.y = gf.y * pc.y + gi.y * gg.y;  hd.y = go.y * tanhf(c.y);
    c.z = gf.z * pc.z + gi.z * gg.z;  hd.z = go.z * tanhf(c.z);
    c.w = gf.w * pc.w + gi.w * gg.w;  hd.w = go.w * tanhf(c.w);
    cell[idx] = c;
    hidden[idx] = hd;
    __half2* a3 = (__half2*)g_A3;     // fp16 hidden -> stage-3 A cols [0,1024)
    a3[m * 1024 + h4 * 2]     = __floats2half2_rn(hd.x, hd.y);
    a3[m * 1024 + h4 * 2 + 1] = __floats2half2_rn(hd.z, hd.w);
}

extern "C" void kernel_launch(void* const* d_in, const int* in_sizes, int n_in,
                              void* d_out, int out_size)
{
    const float* emb = (const float*)d_in[0];
    const float* hid = (const float*)d_in[1];
    const float* pc  = (const float*)d_in[2];
    const float* ctx = (const float*)d_in[3];
    const float* Wi = (const float*)d_in[4];  const float* bi = (const float*)d_in[5];
    const float* Wf = (const float*)d_in[6];  const float* bf = (const float*)d_in[7];
    const float* Wo = (const float*)d_in[8];  const float* bo = (const float*)d_in[9];
    const float* Wg = (const float*)d_in[10]; const float* bg = (const float*)d_in[11];
    const float* Wc = (const float*)d_in[12]; const float* bc = (const float*)d_in[13];
    const float* Wh = (const float*)d_in[14]; const float* bh = (const float*)d_in[15];
    const float* Wp = (const float*)d_in[16]; const float* bp = (const float*)d_in[17];

    const int B = 4096, E = 1024, H = 1024;
    float* out    = (float*)d_out;
    float* pred   = out;
    float* hidden = out + (size_t)B * E;
    float* cell   = out + (size_t)B * E + (size_t)B * H;

    __half *A1, *W1, *A3, *W3, *Wpr, *resid;
    float *gates, *bias_hc;
    cudaGetSymbolAddress((void**)&A1, g_A1);
    cudaGetSymbolAddress((void**)&W1, g_W1);
    cudaGetSymbolAddress((void**)&gates, g_gates);
    cudaGetSymbolAddress((void**)&A3, g_A3);
    cudaGetSymbolAddress((void**)&W3, g_W3);
    cudaGetSymbolAddress((void**)&Wpr, g_Wp);
    cudaGetSymbolAddress((void**)&resid, g_resid);
    cudaGetSymbolAddress((void**)&bias_hc, g_bias_hc);

    cudaFuncSetAttribute(gemm_mma<0>, cudaFuncAttributeMaxDynamicSharedMemorySize, SMEM_BYTES);
    cudaFuncSetAttribute(gemm_mma<1>, cudaFuncAttributeMaxDynamicSharedMemorySize, SMEM_BYTES);
    cudaFuncSetAttribute(gemm_mma<2>, cudaFuncAttributeMaxDynamicSharedMemorySize, SMEM_BYTES);

    // Prep passes (fp16 operand build)
    prep_A1<<<(4096 * 768 + 255) / 256, 256>>>((const float4*)emb, (const float4*)hid,
                                               (const float4*)ctx);
    prep_W1<<<(4096 * 768 + 255) / 256, 256>>>((const float4*)Wi, (const float4*)Wf,
                                               (const float4*)Wo, (const float4*)Wg);
    prep_W3<<<(1024 * 512 + 255) / 256, 256>>>((const float4*)Wh, (const float4*)Wc, bh, bc);
    prep_Wp<<<(1024 * 256 + 255) / 256, 256>>>((const float4*)Wp);

    // Stage 1: gates = act(A1 @ W1^T + b)   M=4096 N=4096 K=3072
    {
        GArgs a = {};
        a.A = A1; a.B = W1;
        a.bias[0] = bi; a.bias[1] = bf; a.bias[2] = bo; a.bias[3] = bg;
        a.out = gates; a.K = 3072; a.Nout = 4096;
        gemm_mma<0><<<dim3(32, 16), 256, SMEM_BYTES>>>(a);
    }
    // Stage 2: pointwise (also emits fp16 hidden into A3)
    lstm_pointwise<<<4096, 256>>>((const float4*)gates, (const float4*)pc,
                                  (float4*)hidden, (float4*)cell);
    // Stage 3: resid = half(emb + A3 @ W3^T + bias_hc)   M=4096 N=1024 K=2048
    {
        GArgs a = {};
        a.A = A3; a.B = W3;
        a.bias[0] = bias_hc;
        a.add = emb;
        a.outh = resid; a.K = 2048; a.Nout = 1024;
        gemm_mma<1><<<dim3(32, 4), 256, SMEM_BYTES>>>(a);
    }
    // Stage 4: pred = resid @ Wp^T + bp   M=4096 N=1024 K=1024
    {
        GArgs a = {};
        a.A = resid; a.B = Wpr;
        a.bias[0] = bp;
        a.out = pred; a.K = 1024; a.Nout = 1024;
        gemm_mma<2><<<dim3(32, 4), 256, SMEM_BYTES>>>(a);
    }
}